// round 14
// baseline (speedup 1.0000x reference)
#include <cuda_runtime.h>
#include <cuda_bf16.h>

// Problem constants
#define BATCH 4
#define SEQ   2048
#define DIM   1024
#define MQ    (BATCH * SEQ)          // 8192 rows of Q/K/V

// GEMM tiling
#define BM 128
#define BN 128
#define BK 16
#define TM 8
#define TN 8
#define NTHREADS 256                  // (BM/TM)*(BN/TN)

// ---------------------------------------------------------------------------
// Scratch (no allocation allowed: __device__ globals)
// ---------------------------------------------------------------------------
__device__ float g_Q[(size_t)MQ * DIM];                 // 32 MB
__device__ float g_K[(size_t)MQ * DIM];                 // 32 MB
__device__ float g_V[(size_t)MQ * DIM];                 // 32 MB
__device__ float g_S[(size_t)BATCH * SEQ * SEQ];        // 64 MB

// ---------------------------------------------------------------------------
// Tiled SGEMM: C[M,N] = alpha * A[M,K] * op(B)
//   TRANS_B = false: B is [K,N] row-major (ldb = N)
//   TRANS_B = true : B is [N,K] row-major (ldb = K), used as B^T
// Batched via blockIdx.z with element strides. All dims multiples of tiles.
// ---------------------------------------------------------------------------
template <bool TRANS_B>
__global__ __launch_bounds__(NTHREADS, 2)
void sgemm_kernel(const float* __restrict__ A,
                  const float* __restrict__ B,
                  float* __restrict__ C,
                  int M, int N, int K,
                  long long strideA, long long strideB, long long strideC,
                  float alpha)
{
    __shared__ float As[BK][BM];
    __shared__ float Bs[BK][BN];

    A += (long long)blockIdx.z * strideA;
    B += (long long)blockIdx.z * strideB;
    C += (long long)blockIdx.z * strideC;

    const int block_m = blockIdx.y * BM;
    const int block_n = blockIdx.x * BN;

    const int tid = threadIdx.x;
    const int tm = (tid >> 4) * TM;   // 0..120
    const int tn = (tid & 15) * TN;   // 0..120

    float acc[TM][TN];
    #pragma unroll
    for (int i = 0; i < TM; i++)
        #pragma unroll
        for (int j = 0; j < TN; j++)
            acc[i][j] = 0.0f;

    for (int k0 = 0; k0 < K; k0 += BK) {
        // --- load A tile: BM x BK, store transposed As[k][m] ---
        #pragma unroll
        for (int it = 0; it < 2; it++) {
            int l = tid + it * NTHREADS;          // 0..511
            int r = l >> 2;                        // 0..127 (m)
            int c = (l & 3) << 2;                  // 0,4,8,12 (k)
            float4 v = *(const float4*)(A + (long long)(block_m + r) * K + k0 + c);
            As[c + 0][r] = v.x;
            As[c + 1][r] = v.y;
            As[c + 2][r] = v.z;
            As[c + 3][r] = v.w;
        }
        // --- load B tile ---
        if (!TRANS_B) {
            // B[K,N]: rows k0..k0+15, cols block_n..block_n+127
            #pragma unroll
            for (int it = 0; it < 2; it++) {
                int l = tid + it * NTHREADS;       // 0..511
                int r = l >> 5;                    // 0..15 (k)
                int c = (l & 31) << 2;             // 0..124 (n)
                float4 v = *(const float4*)(B + (long long)(k0 + r) * N + block_n + c);
                *(float4*)&Bs[r][c] = v;
            }
        } else {
            // B[N,K] used as B^T: rows block_n..+127 (n), cols k0..+15 (k)
            #pragma unroll
            for (int it = 0; it < 2; it++) {
                int l = tid + it * NTHREADS;
                int r = l >> 2;                    // 0..127 (n)
                int c = (l & 3) << 2;              // k
                float4 v = *(const float4*)(B + (long long)(block_n + r) * K + k0 + c);
                Bs[c + 0][r] = v.x;
                Bs[c + 1][r] = v.y;
                Bs[c + 2][r] = v.z;
                Bs[c + 3][r] = v.w;
            }
        }
        __syncthreads();

        // --- compute ---
        #pragma unroll
        for (int kk = 0; kk < BK; kk++) {
            float a_reg[TM], b_reg[TN];
            *(float4*)&a_reg[0] = *(const float4*)&As[kk][tm];
            *(float4*)&a_reg[4] = *(const float4*)&As[kk][tm + 4];
            *(float4*)&b_reg[0] = *(const float4*)&Bs[kk][tn];
            *(float4*)&b_reg[4] = *(const float4*)&Bs[kk][tn + 4];
            #pragma unroll
            for (int i = 0; i < TM; i++)
                #pragma unroll
                for (int j = 0; j < TN; j++)
                    acc[i][j] = fmaf(a_reg[i], b_reg[j], acc[i][j]);
        }
        __syncthreads();
    }

    // --- epilogue: scaled float4 stores ---
    #pragma unroll
    for (int i = 0; i < TM; i++) {
        float* crow = C + (long long)(block_m + tm + i) * N + block_n + tn;
        #pragma unroll
        for (int j = 0; j < TN; j += 4) {
            float4 v;
            v.x = acc[i][j + 0] * alpha;
            v.y = acc[i][j + 1] * alpha;
            v.z = acc[i][j + 2] * alpha;
            v.w = acc[i][j + 3] * alpha;
            *(float4*)(crow + j) = v;
        }
    }
}

// ---------------------------------------------------------------------------
// Row-wise softmax in place. One block (256 threads) per row of `ncols`.
// ---------------------------------------------------------------------------
__global__ void softmax_kernel(float* __restrict__ S, int ncols)
{
    float* p = S + (long long)blockIdx.x * ncols;
    const int tid = threadIdx.x;
    __shared__ float red[32];

    // --- max ---
    float m = -1e30f;
    for (int c = tid; c < ncols; c += blockDim.x) m = fmaxf(m, p[c]);
    #pragma unroll
    for (int o = 16; o; o >>= 1) m = fmaxf(m, __shfl_xor_sync(0xFFFFFFFFu, m, o));
    if ((tid & 31) == 0) red[tid >> 5] = m;
    __syncthreads();
    if (tid < 32) {
        float v = (tid < (int)(blockDim.x >> 5)) ? red[tid] : -1e30f;
        #pragma unroll
        for (int o = 16; o; o >>= 1) v = fmaxf(v, __shfl_xor_sync(0xFFFFFFFFu, v, o));
        red[tid] = v;
    }
    __syncthreads();
    m = red[0];
    __syncthreads();

    // --- exp + sum ---
    float s = 0.0f;
    for (int c = tid; c < ncols; c += blockDim.x) {
        float e = __expf(p[c] - m);
        p[c] = e;
        s += e;
    }
    #pragma unroll
    for (int o = 16; o; o >>= 1) s += __shfl_xor_sync(0xFFFFFFFFu, s, o);
    if ((tid & 31) == 0) red[tid >> 5] = s;
    __syncthreads();
    if (tid < 32) {
        float v = (tid < (int)(blockDim.x >> 5)) ? red[tid] : 0.0f;
        #pragma unroll
        for (int o = 16; o; o >>= 1) v += __shfl_xor_sync(0xFFFFFFFFu, v, o);
        red[tid] = v;
    }
    __syncthreads();
    const float inv = 1.0f / red[0];

    // --- normalize ---
    for (int c = tid; c < ncols; c += blockDim.x) p[c] *= inv;
}

// ---------------------------------------------------------------------------
// kernel_launch
// ---------------------------------------------------------------------------
extern "C" void kernel_launch(void* const* d_in, const int* in_sizes, int n_in,
                              void* d_out, int out_size)
{
    const float* x  = (const float*)d_in[0];   // [4, 2048, 1024]
    const float* wq = (const float*)d_in[1];   // [1024, 1024]
    const float* wk = (const float*)d_in[2];
    const float* wv = (const float*)d_in[3];
    float* out = (float*)d_out;                // [4, 2048, 1024]

    float *Q, *K, *V, *S;
    cudaGetSymbolAddress((void**)&Q, g_Q);
    cudaGetSymbolAddress((void**)&K, g_K);
    cudaGetSymbolAddress((void**)&V, g_V);
    cudaGetSymbolAddress((void**)&S, g_S);

    const float inv_sqrt_d = 0.03125f;  // 1/sqrt(1024)

    // 1) QKV projections: [8192,1024] = [8192,1024] x [1024,1024]  (NN)
    {
        dim3 grid(DIM / BN, MQ / BM, 1);
        sgemm_kernel<false><<<grid, NTHREADS>>>(x, wq, Q, MQ, DIM, DIM, 0, 0, 0, 1.0f);
        sgemm_kernel<false><<<grid, NTHREADS>>>(x, wk, K, MQ, DIM, DIM, 0, 0, 0, 1.0f);
        sgemm_kernel<false><<<grid, NTHREADS>>>(x, wv, V, MQ, DIM, DIM, 0, 0, 0, 1.0f);
    }

    // 2) Scores: per batch, S[2048,2048] = (1/32) * Q[2048,1024] * K^T  (NT)
    {
        dim3 grid(SEQ / BN, SEQ / BM, BATCH);
        sgemm_kernel<true><<<grid, NTHREADS>>>(
            Q, K, S, SEQ, SEQ, DIM,
            (long long)SEQ * DIM, (long long)SEQ * DIM, (long long)SEQ * SEQ,
            inv_sqrt_d);
    }

    // 3) Softmax over each of the 8192 rows of length 2048
    softmax_kernel<<<BATCH * SEQ, 256>>>(S, SEQ);

    // 4) Output: per batch, out[2048,1024] = P[2048,2048] * V[2048,1024]  (NN)
    {
        dim3 grid(DIM / BN, SEQ / BM, BATCH);
        sgemm_kernel<false><<<grid, NTHREADS>>>(
            S, V, out, SEQ, DIM, SEQ,
            (long long)SEQ * SEQ, (long long)SEQ * DIM, (long long)SEQ * DIM,
            1.0f);
    }
}

// round 15
// speedup vs baseline: 1.0264x; 1.0264x over previous
#include <cuda_runtime.h>
#include <cuda_bf16.h>

// Problem constants
#define BATCH 4
#define SEQ   2048
#define DIM   1024
#define MQ    (BATCH * SEQ)          // 8192 rows of Q/K/V

// GEMM tiling
#define BM 128
#define BN 128
#define BK 16
#define TM 8
#define TN 8
#define NTHREADS 256                  // (BM/TM)*(BN/TN)

// ---------------------------------------------------------------------------
// Scratch (no allocation allowed: __device__ globals)
// ---------------------------------------------------------------------------
__device__ float g_Q[(size_t)MQ * DIM];                 // 32 MB
__device__ float g_K[(size_t)MQ * DIM];                 // 32 MB
__device__ float g_V[(size_t)MQ * DIM];                 // 32 MB
__device__ float g_S[(size_t)BATCH * SEQ * SEQ];        // 64 MB

// ---------------------------------------------------------------------------
// Tiled SGEMM: C[M,N] = alpha * A[M,K] * op(B)
//   TRANS_B = false: B is [K,N] row-major (ldb = N)
//   TRANS_B = true : B is [N,K] row-major (ldb = K), used as B^T
// Batched via blockIdx.z with element strides. All dims multiples of tiles.
// ---------------------------------------------------------------------------
template <bool TRANS_B>
__global__ __launch_bounds__(NTHREADS, 2)
void sgemm_kernel(const float* __restrict__ A,
                  const float* __restrict__ B,
                  float* __restrict__ C,
                  int M, int N, int K,
                  long long strideA, long long strideB, long long strideC,
                  float alpha)
{
    __shared__ float As[BK][BM];
    __shared__ float Bs[BK][BN];

    A += (long long)blockIdx.z * strideA;
    B += (long long)blockIdx.z * strideB;
    C += (long long)blockIdx.z * strideC;

    const int block_m = blockIdx.y * BM;
    const int block_n = blockIdx.x * BN;

    const int tid = threadIdx.x;
    const int tm = (tid >> 4) * TM;   // 0..120
    const int tn = (tid & 15) * TN;   // 0..120

    float acc[TM][TN];
    #pragma unroll
    for (int i = 0; i < TM; i++)
        #pragma unroll
        for (int j = 0; j < TN; j++)
            acc[i][j] = 0.0f;

    for (int k0 = 0; k0 < K; k0 += BK) {
        // --- load A tile: BM x BK, store transposed As[k][m] ---
        #pragma unroll
        for (int it = 0; it < 2; it++) {
            int l = tid + it * NTHREADS;          // 0..511
            int r = l >> 2;                        // 0..127 (m)
            int c = (l & 3) << 2;                  // 0,4,8,12 (k)
            float4 v = *(const float4*)(A + (long long)(block_m + r) * K + k0 + c);
            As[c + 0][r] = v.x;
            As[c + 1][r] = v.y;
            As[c + 2][r] = v.z;
            As[c + 3][r] = v.w;
        }
        // --- load B tile ---
        if (!TRANS_B) {
            // B[K,N]: rows k0..k0+15, cols block_n..block_n+127
            #pragma unroll
            for (int it = 0; it < 2; it++) {
                int l = tid + it * NTHREADS;       // 0..511
                int r = l >> 5;                    // 0..15 (k)
                int c = (l & 31) << 2;             // 0..124 (n)
                float4 v = *(const float4*)(B + (long long)(k0 + r) * N + block_n + c);
                *(float4*)&Bs[r][c] = v;
            }
        } else {
            // B[N,K] used as B^T: rows block_n..+127 (n), cols k0..+15 (k)
            #pragma unroll
            for (int it = 0; it < 2; it++) {
                int l = tid + it * NTHREADS;
                int r = l >> 2;                    // 0..127 (n)
                int c = (l & 3) << 2;              // k
                float4 v = *(const float4*)(B + (long long)(block_n + r) * K + k0 + c);
                Bs[c + 0][r] = v.x;
                Bs[c + 1][r] = v.y;
                Bs[c + 2][r] = v.z;
                Bs[c + 3][r] = v.w;
            }
        }
        __syncthreads();

        // --- compute ---
        #pragma unroll
        for (int kk = 0; kk < BK; kk++) {
            float a_reg[TM], b_reg[TN];
            *(float4*)&a_reg[0] = *(const float4*)&As[kk][tm];
            *(float4*)&a_reg[4] = *(const float4*)&As[kk][tm + 4];
            *(float4*)&b_reg[0] = *(const float4*)&Bs[kk][tn];
            *(float4*)&b_reg[4] = *(const float4*)&Bs[kk][tn + 4];
            #pragma unroll
            for (int i = 0; i < TM; i++)
                #pragma unroll
                for (int j = 0; j < TN; j++)
                    acc[i][j] = fmaf(a_reg[i], b_reg[j], acc[i][j]);
        }
        __syncthreads();
    }

    // --- epilogue: scaled float4 stores ---
    #pragma unroll
    for (int i = 0; i < TM; i++) {
        float* crow = C + (long long)(block_m + tm + i) * N + block_n + tn;
        #pragma unroll
        for (int j = 0; j < TN; j += 4) {
            float4 v;
            v.x = acc[i][j + 0] * alpha;
            v.y = acc[i][j + 1] * alpha;
            v.z = acc[i][j + 2] * alpha;
            v.w = acc[i][j + 3] * alpha;
            *(float4*)(crow + j) = v;
        }
    }
}

// ---------------------------------------------------------------------------
// Row-wise softmax in place. One block (256 threads) per row of `ncols`.
// ---------------------------------------------------------------------------
__global__ void softmax_kernel(float* __restrict__ S, int ncols)
{
    float* p = S + (long long)blockIdx.x * ncols;
    const int tid = threadIdx.x;
    __shared__ float red[32];

    // --- max ---
    float m = -1e30f;
    for (int c = tid; c < ncols; c += blockDim.x) m = fmaxf(m, p[c]);
    #pragma unroll
    for (int o = 16; o; o >>= 1) m = fmaxf(m, __shfl_xor_sync(0xFFFFFFFFu, m, o));
    if ((tid & 31) == 0) red[tid >> 5] = m;
    __syncthreads();
    if (tid < 32) {
        float v = (tid < (int)(blockDim.x >> 5)) ? red[tid] : -1e30f;
        #pragma unroll
        for (int o = 16; o; o >>= 1) v = fmaxf(v, __shfl_xor_sync(0xFFFFFFFFu, v, o));
        red[tid] = v;
    }
    __syncthreads();
    m = red[0];
    __syncthreads();

    // --- exp + sum ---
    float s = 0.0f;
    for (int c = tid; c < ncols; c += blockDim.x) {
        float e = __expf(p[c] - m);
        p[c] = e;
        s += e;
    }
    #pragma unroll
    for (int o = 16; o; o >>= 1) s += __shfl_xor_sync(0xFFFFFFFFu, s, o);
    if ((tid & 31) == 0) red[tid >> 5] = s;
    __syncthreads();
    if (tid < 32) {
        float v = (tid < (int)(blockDim.x >> 5)) ? red[tid] : 0.0f;
        #pragma unroll
        for (int o = 16; o; o >>= 1) v += __shfl_xor_sync(0xFFFFFFFFu, v, o);
        red[tid] = v;
    }
    __syncthreads();
    const float inv = 1.0f / red[0];

    // --- normalize ---
    for (int c = tid; c < ncols; c += blockDim.x) p[c] *= inv;
}

// ---------------------------------------------------------------------------
// kernel_launch
// ---------------------------------------------------------------------------
extern "C" void kernel_launch(void* const* d_in, const int* in_sizes, int n_in,
                              void* d_out, int out_size)
{
    const float* x  = (const float*)d_in[0];   // [4, 2048, 1024]
    const float* wq = (const float*)d_in[1];   // [1024, 1024]
    const float* wk = (const float*)d_in[2];
    const float* wv = (const float*)d_in[3];
    float* out = (float*)d_out;                // [4, 2048, 1024]

    float *Q, *K, *V, *S;
    cudaGetSymbolAddress((void**)&Q, g_Q);
    cudaGetSymbolAddress((void**)&K, g_K);
    cudaGetSymbolAddress((void**)&V, g_V);
    cudaGetSymbolAddress((void**)&S, g_S);

    const float inv_sqrt_d = 0.03125f;  // 1/sqrt(1024)

    // 1) QKV projections: [8192,1024] = [8192,1024] x [1024,1024]  (NN)
    {
        dim3 grid(DIM / BN, MQ / BM, 1);
        sgemm_kernel<false><<<grid, NTHREADS>>>(x, wq, Q, MQ, DIM, DIM, 0, 0, 0, 1.0f);
        sgemm_kernel<false><<<grid, NTHREADS>>>(x, wk, K, MQ, DIM, DIM, 0, 0, 0, 1.0f);
        sgemm_kernel<false><<<grid, NTHREADS>>>(x, wv, V, MQ, DIM, DIM, 0, 0, 0, 1.0f);
    }

    // 2) Scores: per batch, S[2048,2048] = (1/32) * Q[2048,1024] * K^T  (NT)
    {
        dim3 grid(SEQ / BN, SEQ / BM, BATCH);
        sgemm_kernel<true><<<grid, NTHREADS>>>(
            Q, K, S, SEQ, SEQ, DIM,
            (long long)SEQ * DIM, (long long)SEQ * DIM, (long long)SEQ * SEQ,
            inv_sqrt_d);
    }

    // 3) Softmax over each of the 8192 rows of length 2048
    softmax_kernel<<<BATCH * SEQ, 256>>>(S, SEQ);

    // 4) Output: per batch, out[2048,1024] = P[2048,2048] * V[2048,1024]  (NN)
    {
        dim3 grid(DIM / BN, SEQ / BM, BATCH);
        sgemm_kernel<false><<<grid, NTHREADS>>>(
            S, V, out, SEQ, DIM, SEQ,
            (long long)SEQ * SEQ, (long long)SEQ * DIM, (long long)SEQ * DIM,
            1.0f);
    }
}

// round 16
// speedup vs baseline: 1.0277x; 1.0013x over previous
#include <cuda_runtime.h>
#include <cuda_bf16.h>

// Problem constants
#define BATCH 4
#define SEQ   2048
#define DIM   1024
#define MQ    (BATCH * SEQ)          // 8192 rows of Q/K/V

// GEMM tiling
#define BM 128
#define BN 128
#define BK 16
#define TM 8
#define TN 8
#define NTHREADS 256                  // (BM/TM)*(BN/TN)

// ---------------------------------------------------------------------------
// Scratch (no allocation allowed: __device__ globals)
// ---------------------------------------------------------------------------
__device__ float g_Q[(size_t)MQ * DIM];                 // 32 MB
__device__ float g_K[(size_t)MQ * DIM];                 // 32 MB
__device__ float g_V[(size_t)MQ * DIM];                 // 32 MB
__device__ float g_S[(size_t)BATCH * SEQ * SEQ];        // 64 MB

// ---------------------------------------------------------------------------
// Tiled SGEMM: C[M,N] = alpha * A[M,K] * op(B)
//   TRANS_B = false: B is [K,N] row-major (ldb = N)
//   TRANS_B = true : B is [N,K] row-major (ldb = K), used as B^T
// Batched via blockIdx.z with element strides. All dims multiples of tiles.
// ---------------------------------------------------------------------------
template <bool TRANS_B>
__global__ __launch_bounds__(NTHREADS, 2)
void sgemm_kernel(const float* __restrict__ A,
                  const float* __restrict__ B,
                  float* __restrict__ C,
                  int M, int N, int K,
                  long long strideA, long long strideB, long long strideC,
                  float alpha)
{
    __shared__ float As[BK][BM];
    __shared__ float Bs[BK][BN];

    A += (long long)blockIdx.z * strideA;
    B += (long long)blockIdx.z * strideB;
    C += (long long)blockIdx.z * strideC;

    const int block_m = blockIdx.y * BM;
    const int block_n = blockIdx.x * BN;

    const int tid = threadIdx.x;
    const int tm = (tid >> 4) * TM;   // 0..120
    const int tn = (tid & 15) * TN;   // 0..120

    float acc[TM][TN];
    #pragma unroll
    for (int i = 0; i < TM; i++)
        #pragma unroll
        for (int j = 0; j < TN; j++)
            acc[i][j] = 0.0f;

    for (int k0 = 0; k0 < K; k0 += BK) {
        // --- load A tile: BM x BK, store transposed As[k][m] ---
        #pragma unroll
        for (int it = 0; it < 2; it++) {
            int l = tid + it * NTHREADS;          // 0..511
            int r = l >> 2;                        // 0..127 (m)
            int c = (l & 3) << 2;                  // 0,4,8,12 (k)
            float4 v = *(const float4*)(A + (long long)(block_m + r) * K + k0 + c);
            As[c + 0][r] = v.x;
            As[c + 1][r] = v.y;
            As[c + 2][r] = v.z;
            As[c + 3][r] = v.w;
        }
        // --- load B tile ---
        if (!TRANS_B) {
            // B[K,N]: rows k0..k0+15, cols block_n..block_n+127
            #pragma unroll
            for (int it = 0; it < 2; it++) {
                int l = tid + it * NTHREADS;       // 0..511
                int r = l >> 5;                    // 0..15 (k)
                int c = (l & 31) << 2;             // 0..124 (n)
                float4 v = *(const float4*)(B + (long long)(k0 + r) * N + block_n + c);
                *(float4*)&Bs[r][c] = v;
            }
        } else {
            // B[N,K] used as B^T: rows block_n..+127 (n), cols k0..+15 (k)
            #pragma unroll
            for (int it = 0; it < 2; it++) {
                int l = tid + it * NTHREADS;
                int r = l >> 2;                    // 0..127 (n)
                int c = (l & 3) << 2;              // k
                float4 v = *(const float4*)(B + (long long)(block_n + r) * K + k0 + c);
                Bs[c + 0][r] = v.x;
                Bs[c + 1][r] = v.y;
                Bs[c + 2][r] = v.z;
                Bs[c + 3][r] = v.w;
            }
        }
        __syncthreads();

        // --- compute ---
        #pragma unroll
        for (int kk = 0; kk < BK; kk++) {
            float a_reg[TM], b_reg[TN];
            *(float4*)&a_reg[0] = *(const float4*)&As[kk][tm];
            *(float4*)&a_reg[4] = *(const float4*)&As[kk][tm + 4];
            *(float4*)&b_reg[0] = *(const float4*)&Bs[kk][tn];
            *(float4*)&b_reg[4] = *(const float4*)&Bs[kk][tn + 4];
            #pragma unroll
            for (int i = 0; i < TM; i++)
                #pragma unroll
                for (int j = 0; j < TN; j++)
                    acc[i][j] = fmaf(a_reg[i], b_reg[j], acc[i][j]);
        }
        __syncthreads();
    }

    // --- epilogue: scaled float4 stores ---
    #pragma unroll
    for (int i = 0; i < TM; i++) {
        float* crow = C + (long long)(block_m + tm + i) * N + block_n + tn;
        #pragma unroll
        for (int j = 0; j < TN; j += 4) {
            float4 v;
            v.x = acc[i][j + 0] * alpha;
            v.y = acc[i][j + 1] * alpha;
            v.z = acc[i][j + 2] * alpha;
            v.w = acc[i][j + 3] * alpha;
            *(float4*)(crow + j) = v;
        }
    }
}

// ---------------------------------------------------------------------------
// Row-wise softmax in place. One block (256 threads) per row of `ncols`.
// ---------------------------------------------------------------------------
__global__ void softmax_kernel(float* __restrict__ S, int ncols)
{
    float* p = S + (long long)blockIdx.x * ncols;
    const int tid = threadIdx.x;
    __shared__ float red[32];

    // --- max ---
    float m = -1e30f;
    for (int c = tid; c < ncols; c += blockDim.x) m = fmaxf(m, p[c]);
    #pragma unroll
    for (int o = 16; o; o >>= 1) m = fmaxf(m, __shfl_xor_sync(0xFFFFFFFFu, m, o));
    if ((tid & 31) == 0) red[tid >> 5] = m;
    __syncthreads();
    if (tid < 32) {
        float v = (tid < (int)(blockDim.x >> 5)) ? red[tid] : -1e30f;
        #pragma unroll
        for (int o = 16; o; o >>= 1) v = fmaxf(v, __shfl_xor_sync(0xFFFFFFFFu, v, o));
        red[tid] = v;
    }
    __syncthreads();
    m = red[0];
    __syncthreads();

    // --- exp + sum ---
    float s = 0.0f;
    for (int c = tid; c < ncols; c += blockDim.x) {
        float e = __expf(p[c] - m);
        p[c] = e;
        s += e;
    }
    #pragma unroll
    for (int o = 16; o; o >>= 1) s += __shfl_xor_sync(0xFFFFFFFFu, s, o);
    if ((tid & 31) == 0) red[tid >> 5] = s;
    __syncthreads();
    if (tid < 32) {
        float v = (tid < (int)(blockDim.x >> 5)) ? red[tid] : 0.0f;
        #pragma unroll
        for (int o = 16; o; o >>= 1) v += __shfl_xor_sync(0xFFFFFFFFu, v, o);
        red[tid] = v;
    }
    __syncthreads();
    const float inv = 1.0f / red[0];

    // --- normalize ---
    for (int c = tid; c < ncols; c += blockDim.x) p[c] *= inv;
}

// ---------------------------------------------------------------------------
// kernel_launch
// ---------------------------------------------------------------------------
extern "C" void kernel_launch(void* const* d_in, const int* in_sizes, int n_in,
                              void* d_out, int out_size)
{
    const float* x  = (const float*)d_in[0];   // [4, 2048, 1024]
    const float* wq = (const float*)d_in[1];   // [1024, 1024]
    const float* wk = (const float*)d_in[2];
    const float* wv = (const float*)d_in[3];
    float* out = (float*)d_out;                // [4, 2048, 1024]

    float *Q, *K, *V, *S;
    cudaGetSymbolAddress((void**)&Q, g_Q);
    cudaGetSymbolAddress((void**)&K, g_K);
    cudaGetSymbolAddress((void**)&V, g_V);
    cudaGetSymbolAddress((void**)&S, g_S);

    const float inv_sqrt_d = 0.03125f;  // 1/sqrt(1024)

    // 1) QKV projections: [8192,1024] = [8192,1024] x [1024,1024]  (NN)
    {
        dim3 grid(DIM / BN, MQ / BM, 1);
        sgemm_kernel<false><<<grid, NTHREADS>>>(x, wq, Q, MQ, DIM, DIM, 0, 0, 0, 1.0f);
        sgemm_kernel<false><<<grid, NTHREADS>>>(x, wk, K, MQ, DIM, DIM, 0, 0, 0, 1.0f);
        sgemm_kernel<false><<<grid, NTHREADS>>>(x, wv, V, MQ, DIM, DIM, 0, 0, 0, 1.0f);
    }

    // 2) Scores: per batch, S[2048,2048] = (1/32) * Q[2048,1024] * K^T  (NT)
    {
        dim3 grid(SEQ / BN, SEQ / BM, BATCH);
        sgemm_kernel<true><<<grid, NTHREADS>>>(
            Q, K, S, SEQ, SEQ, DIM,
            (long long)SEQ * DIM, (long long)SEQ * DIM, (long long)SEQ * SEQ,
            inv_sqrt_d);
    }

    // 3) Softmax over each of the 8192 rows of length 2048
    softmax_kernel<<<BATCH * SEQ, 256>>>(S, SEQ);

    // 4) Output: per batch, out[2048,1024] = P[2048,2048] * V[2048,1024]  (NN)
    {
        dim3 grid(DIM / BN, SEQ / BM, BATCH);
        sgemm_kernel<false><<<grid, NTHREADS>>>(
            S, V, out, SEQ, DIM, SEQ,
            (long long)SEQ * SEQ, (long long)SEQ * DIM, (long long)SEQ * DIM,
            1.0f);
    }
}